// round 11
// baseline (speedup 1.0000x reference)
#include <cuda_runtime.h>

// GAE backward scan as a parallel suffix scan of affine maps.
// gae_t = delta_t + c_t * gae_{t+1},  c_t = GAMMA*LMBDA*nd_t  (nd in {0,1})
//
// R11: persistent CTAs + cp.async double-buffered smem prefetch.
// R7's persistent loop failed because __syncthreads serialized next-row
// loads behind the current scan; here row i+1 streams into smem via LDGSTS
// while row i computes. Each thread reads only its own cp.async'd bytes,
// so wait_group alone orders the data -- no extra barriers.
// Locked config: 512 thr, VPT=4, 3 CTAs/SM (64KB smem), .cs stores.

#define GAMMA 0.99f
#define LMBDA 0.95f
#define KCOEF (GAMMA * LMBDA)   // 0.9405f

constexpr int T_LEN   = 2048;
constexpr int THREADS = 512;
constexpr int VPT     = T_LEN / THREADS;  // 4
constexpr int NWARP   = THREADS / 32;     // 16
constexpr int GRID    = 3 * 152;          // 3 CTAs/SM * 152 SMs
constexpr int ARR_BYTES   = T_LEN * 4;        // 8192 per array per row
constexpr int STAGE_BYTES = 4 * ARR_BYTES;    // 32768 per stage
constexpr size_t SMEM_BYTES = 2 * STAGE_BYTES; // 65536 (also pins 3 CTAs/SM)

#define CP_ASYNC16(dst, src) \
    asm volatile("cp.async.cg.shared.global [%0], [%1], 16;" \
                 :: "r"(dst), "l"(src) : "memory")
#define CP_COMMIT() asm volatile("cp.async.commit_group;" ::: "memory")
#define CP_WAIT(n)  asm volatile("cp.async.wait_group %0;" :: "n"(n) : "memory")

__global__ __launch_bounds__(THREADS)
void gae_kernel(const float* __restrict__ reward,
                const int*   __restrict__ terminated,
                const float* __restrict__ value,
                const float* __restrict__ next_value,
                float*       __restrict__ adv_out,
                float*       __restrict__ ret_out,
                int B)
{
    extern __shared__ char stage_mem[];
    __shared__ float sA[2][NWARP], sB[2][NWARP], gIn[2][NWARP];

    const int tid  = threadIdx.x;
    const int lane = tid & 31;
    const int warp = tid >> 5;
    const unsigned FULL = 0xffffffffu;
    const int grid = gridDim.x;

    const unsigned s_base =
        (unsigned)__cvta_generic_to_shared(stage_mem) + (unsigned)(tid * 16);

    // ---- Prologue: prefetch first row into stage 0 ----
    {
        const long long g = (long long)blockIdx.x * T_LEN + (long long)tid * VPT;
        CP_ASYNC16(s_base + 0,             reward     + g);
        CP_ASYNC16(s_base + ARR_BYTES,     value      + g);
        CP_ASYNC16(s_base + 2*ARR_BYTES,   next_value + g);
        CP_ASYNC16(s_base + 3*ARR_BYTES,   terminated + g);
        CP_COMMIT();
    }

    int stage = 0, par = 0;
    for (long long row = blockIdx.x; row < B; row += grid, stage ^= 1, par ^= 1) {
        const bool has_next = (row + grid < B);

        // ---- Issue next row's prefetch into the other stage ----
        if (has_next) {
            const long long g = (row + grid) * T_LEN + (long long)tid * VPT;
            const unsigned d = s_base + (unsigned)((stage ^ 1) * STAGE_BYTES);
            CP_ASYNC16(d + 0,           reward     + g);
            CP_ASYNC16(d + ARR_BYTES,   value      + g);
            CP_ASYNC16(d + 2*ARR_BYTES, next_value + g);
            CP_ASYNC16(d + 3*ARR_BYTES, terminated + g);
            CP_COMMIT();
            CP_WAIT(1);   // current stage's group complete (this thread's data)
        } else {
            CP_WAIT(0);
        }

        // ---- Read own 64B slice from smem (LDS.128, conflict-free) ----
        const char* sp = stage_mem + stage * STAGE_BYTES + tid * 16;
        float4 rr = *reinterpret_cast<const float4*>(sp + 0);
        float4 vv = *reinterpret_cast<const float4*>(sp + ARR_BYTES);
        float4 nn = *reinterpret_cast<const float4*>(sp + 2*ARR_BYTES);
        int4   tt = *reinterpret_cast<const int4*>  (sp + 3*ARR_BYTES);

        float v[VPT] = {vv.x, vv.y, vv.z, vv.w};
        float delta[VPT];
        unsigned mask = 0;
        delta[0] = (tt.x == 0) ? fmaf(GAMMA, nn.x, rr.x - vv.x) : (rr.x - vv.x);
        delta[1] = (tt.y == 0) ? fmaf(GAMMA, nn.y, rr.y - vv.y) : (rr.y - vv.y);
        delta[2] = (tt.z == 0) ? fmaf(GAMMA, nn.z, rr.z - vv.z) : (rr.z - vv.z);
        delta[3] = (tt.w == 0) ? fmaf(GAMMA, nn.w, rr.w - vv.w) : (rr.w - vv.w);
        mask |= (tt.x == 0 ? 1u : 0u) << 0;
        mask |= (tt.y == 0 ? 1u : 0u) << 1;
        mask |= (tt.z == 0 ? 1u : 0u) << 2;
        mask |= (tt.w == 0 ? 1u : 0u) << 3;

        // ---- Fold chunk into one affine composite ----
        float A = 1.0f, Bc = 0.0f;
        #pragma unroll
        for (int j = 0; j < VPT; ++j) {
            Bc = fmaf(A, delta[j], Bc);
            A  = ((mask >> j) & 1u) ? A * KCOEF : 0.0f;
        }

        // ---- Warp-level inclusive SUFFIX scan ----
        float Ai = A, Bi = Bc;
        #pragma unroll
        for (int off = 1; off < 32; off <<= 1) {
            float Ao = __shfl_down_sync(FULL, Ai, off);
            float Bo = __shfl_down_sync(FULL, Bi, off);
            if (lane + off < 32) {
                Bi = fmaf(Ai, Bo, Bi);
                Ai = Ai * Ao;
            }
        }
        float Ae = __shfl_down_sync(FULL, Ai, 1);
        float Be = __shfl_down_sync(FULL, Bi, 1);
        if (lane == 31) { Ae = 1.0f; Be = 0.0f; }

        // ---- Cross-warp combine (parity double-buffered) ----
        if (lane == 0) { sA[par][warp] = Ai; sB[par][warp] = Bi; }
        __syncthreads();
        if (tid < NWARP) {
            float g = 0.0f;
            #pragma unroll
            for (int w = NWARP - 1; w > 0; --w)
                if (w > tid) g = fmaf(sA[par][w], g, sB[par][w]);
            gIn[par][tid] = g;
        }
        __syncthreads();

        float g = fmaf(Ae, gIn[par][warp], Be);

        // ---- Replay chunk backward ----
        float adv[VPT];
        #pragma unroll
        for (int j = VPT - 1; j >= 0; --j) {
            g = ((mask >> j) & 1u) ? fmaf(KCOEF, g, delta[j]) : delta[j];
            adv[j] = g;
        }

        // ---- Evict-first stores ----
        const long long base = row * T_LEN + (long long)tid * VPT;
        float4 av, rt;
        av.x = adv[0]; av.y = adv[1]; av.z = adv[2]; av.w = adv[3];
        rt.x = av.x + v[0];
        rt.y = av.y + v[1];
        rt.z = av.z + v[2];
        rt.w = av.w + v[3];
        __stcs(reinterpret_cast<float4*>(adv_out + base), av);
        __stcs(reinterpret_cast<float4*>(ret_out + base), rt);
    }
}

extern "C" void kernel_launch(void* const* d_in, const int* in_sizes, int n_in,
                              void* d_out, int out_size)
{
    const float* reward     = (const float*)d_in[0];
    const int*   terminated = (const int*)  d_in[1];
    const float* value      = (const float*)d_in[2];
    const float* next_value = (const float*)d_in[3];

    const int n = in_sizes[0];          // B * T
    const int B = n / T_LEN;

    float* adv_out = (float*)d_out;          // advantages: first n elements
    float* ret_out = (float*)d_out + n;      // returns:    next n elements

    cudaFuncSetAttribute(gae_kernel,
                         cudaFuncAttributeMaxDynamicSharedMemorySize,
                         (int)SMEM_BYTES);

    const int grid = (B < GRID) ? B : GRID;
    gae_kernel<<<grid, THREADS, SMEM_BYTES>>>(reward, terminated, value,
                                              next_value, adv_out, ret_out, B);
}